// round 1
// baseline (speedup 1.0000x reference)
#include <cuda_runtime.h>
#include <cstdint>

// Problem: act (8192 x 4096) f32, w (4096 x 8192) f32  ->  out (8192 x 8192) f32
// Quantized int8 GEMM exactly reproducing the JAX reference.

#define EPSQ 1e-6f
#define CLIPV 127.0f

#define MB 8192   // batch (M)
#define KD 4096   // Cin  (K)
#define ND 8192   // Cout (N)

// ---- scratch (device globals; no allocation allowed) ----
__device__ unsigned int g_amax[KD];                 // max|act| per Cin column (bits of nonneg float)
__device__ unsigned int g_wmax[ND];                 // max|w_scaled| per Cout column
__device__ int8_t g_actq[(size_t)MB * KD];          // quantized activations, row-major [M][K]
__device__ int8_t g_wqT[(size_t)ND * KD];           // quantized weights, TRANSPOSED [N][K]

// ------------------------------------------------------------------
// 0) zero the bound arrays (graph is replayed; atomicMax needs reset)
// ------------------------------------------------------------------
__global__ void k_zero_bounds() {
    int i = blockIdx.x * blockDim.x + threadIdx.x;
    if (i < KD) g_amax[i] = 0u;
    if (i < ND) g_wmax[i] = 0u;
}

// ------------------------------------------------------------------
// 1) per-column max|act|  (columns = Cin)
// ------------------------------------------------------------------
__global__ void k_act_absmax(const float* __restrict__ act) {
    int c  = blockIdx.x * 256 + threadIdx.x;     // column
    int r0 = blockIdx.y * 512;                   // row chunk
    const float* p = act + (size_t)r0 * KD + c;
    float m = 0.f;
#pragma unroll 8
    for (int r = 0; r < 512; ++r)
        m = fmaxf(m, fabsf(p[(size_t)r * KD]));
    atomicMax(&g_amax[c], __float_as_uint(m));   // nonneg float bits order like uint
}

// ------------------------------------------------------------------
// 2) quantize activations -> int8  (row-major, K contiguous)
// ------------------------------------------------------------------
__global__ void k_act_quant(const float* __restrict__ act) {
    const float4* a4 = (const float4*)act;
    char4* q4 = (char4*)g_actq;
    size_t n4 = (size_t)MB * KD / 4;
    size_t stride = (size_t)gridDim.x * blockDim.x;
    for (size_t idx = blockIdx.x * (size_t)blockDim.x + threadIdx.x; idx < n4; idx += stride) {
        float4 v = a4[idx];
        int c = (int)(idx & (KD / 4 - 1)) * 4;   // column of first element
        float s0 = CLIPV / (__uint_as_float(g_amax[c + 0]) + EPSQ);
        float s1 = CLIPV / (__uint_as_float(g_amax[c + 1]) + EPSQ);
        float s2 = CLIPV / (__uint_as_float(g_amax[c + 2]) + EPSQ);
        float s3 = CLIPV / (__uint_as_float(g_amax[c + 3]) + EPSQ);
        char4 o;
        o.x = (char)(int)fminf(fmaxf(rintf(v.x * s0), -CLIPV), CLIPV);
        o.y = (char)(int)fminf(fmaxf(rintf(v.y * s1), -CLIPV), CLIPV);
        o.z = (char)(int)fminf(fmaxf(rintf(v.z * s2), -CLIPV), CLIPV);
        o.w = (char)(int)fminf(fmaxf(rintf(v.w * s3), -CLIPV), CLIPV);
        q4[idx] = o;
    }
}

// ------------------------------------------------------------------
// 3) per-column max|w * inv_act_scale|  (columns = Cout)
// ------------------------------------------------------------------
__global__ void k_w_absmax(const float* __restrict__ w) {
    __shared__ float invs[256];
    int k0 = blockIdx.y * 256;
    {
        float am = __uint_as_float(g_amax[k0 + threadIdx.x]);
        float s  = CLIPV / (am + EPSQ);          // act_scale
        invs[threadIdx.x] = 1.0f / s;            // reference computes 1.0/act_scale
    }
    __syncthreads();
    int n = blockIdx.x * 256 + threadIdx.x;
    const float* p = w + (size_t)k0 * ND + n;
    float m = 0.f;
#pragma unroll 8
    for (int k = 0; k < 256; ++k)
        m = fmaxf(m, fabsf(p[(size_t)k * ND] * invs[k]));
    atomicMax(&g_wmax[n], __float_as_uint(m));
}

// ------------------------------------------------------------------
// 4) quantize weights -> int8, transposed to [N][K]
//    32x32 tile via shared memory
// ------------------------------------------------------------------
__global__ void k_w_quant_T(const float* __restrict__ w) {
    __shared__ int8_t t[32][33];
    int n0 = blockIdx.x * 32, k0 = blockIdx.y * 32;
    int tx = threadIdx.x;          // 0..31 : n within tile
    int ty = threadIdx.y;          // 0..7
    int n = n0 + tx;
    float ws = CLIPV / (__uint_as_float(g_wmax[n]) + EPSQ);
#pragma unroll
    for (int r = 0; r < 4; ++r) {
        int ki = ty * 4 + r;
        int k = k0 + ki;
        float am = __uint_as_float(g_amax[k]);
        float iv = 1.0f / (CLIPV / (am + EPSQ));
        float v = w[(size_t)k * ND + n] * iv;
        float q = fminf(fmaxf(rintf(v * ws), -CLIPV), CLIPV);
        t[ki][tx] = (int8_t)(int)q;
    }
    __syncthreads();
    int idx = ty * 32 + tx;        // 0..255
    int nl = idx >> 3;             // 0..31 : n row within tile
    int wd = idx & 7;              // 0..7  : 4-byte word within 32 k bytes
    uint32_t pk = (uint32_t)(uint8_t)t[wd * 4 + 0][nl]
                | ((uint32_t)(uint8_t)t[wd * 4 + 1][nl] << 8)
                | ((uint32_t)(uint8_t)t[wd * 4 + 2][nl] << 16)
                | ((uint32_t)(uint8_t)t[wd * 4 + 3][nl] << 24);
    *(uint32_t*)&g_wqT[(size_t)(n0 + nl) * KD + k0 + wd * 4] = pk;
}

// ------------------------------------------------------------------
// 5) int8 GEMM via dp4a: C[m][n] = dot(actq[m,:], wqT[n,:])
//    BM=BN=128, BK=64 bytes, 256 threads, 8x8 outputs per thread.
//    Epilogue dequant by 1/w_scale[n].
// ------------------------------------------------------------------
__global__ __launch_bounds__(256, 2)
void k_gemm_dp4a(float* __restrict__ C) {
    __shared__ uint32_t As[16][132];   // [k-word within 64B][m]
    __shared__ uint32_t Bs[16][132];   // [k-word within 64B][n]

    const int Kw = KD / 4;             // 1024 u32 per row
    int tid = threadIdx.x;
    int tm = tid >> 4, tn = tid & 15;  // 16 x 16 thread grid
    int m0 = blockIdx.y * 128, n0 = blockIdx.x * 128;

    const uint4* A128 = (const uint4*)g_actq + (size_t)m0 * (Kw / 4);
    const uint4* B128 = (const uint4*)g_wqT  + (size_t)n0 * (Kw / 4);

    int acc[8][8];
#pragma unroll
    for (int i = 0; i < 8; ++i)
#pragma unroll
        for (int j = 0; j < 8; ++j) acc[i][j] = 0;

    for (int kt = 0; kt < KD / 64; ++kt) {
        int w4 = kt * 4;               // uint4 offset within a row
#pragma unroll
        for (int p = 0; p < 2; ++p) {
            int id  = p * 256 + tid;
            int row = id >> 2;         // 0..127
            int c4  = id & 3;          // which uint4 (covers 4 k-words)
            uint4 va = A128[(size_t)row * (Kw / 4) + w4 + c4];
            As[c4 * 4 + 0][row] = va.x;
            As[c4 * 4 + 1][row] = va.y;
            As[c4 * 4 + 2][row] = va.z;
            As[c4 * 4 + 3][row] = va.w;
            uint4 vb = B128[(size_t)row * (Kw / 4) + w4 + c4];
            Bs[c4 * 4 + 0][row] = vb.x;
            Bs[c4 * 4 + 1][row] = vb.y;
            Bs[c4 * 4 + 2][row] = vb.z;
            Bs[c4 * 4 + 3][row] = vb.w;
        }
        __syncthreads();
#pragma unroll
        for (int kk = 0; kk < 16; ++kk) {
            uint32_t a[8], b[8];
#pragma unroll
            for (int i = 0; i < 8; ++i) a[i] = As[kk][tm * 8 + i];
#pragma unroll
            for (int j = 0; j < 8; ++j) b[j] = Bs[kk][tn * 8 + j];
#pragma unroll
            for (int i = 0; i < 8; ++i)
#pragma unroll
                for (int j = 0; j < 8; ++j)
                    acc[i][j] = __dp4a((int)a[i], (int)b[j], acc[i][j]);
        }
        __syncthreads();
    }

    // epilogue: dequant by per-Cout 1/w_scale
    float dq[8];
#pragma unroll
    for (int j = 0; j < 8; ++j) {
        float s = CLIPV / (__uint_as_float(g_wmax[n0 + tn * 8 + j]) + EPSQ);
        dq[j] = 1.0f / s;
    }
#pragma unroll
    for (int i = 0; i < 8; ++i) {
        float* Crow = C + (size_t)(m0 + tm * 8 + i) * ND + n0 + tn * 8;
        float4 v0, v1;
        v0.x = (float)acc[i][0] * dq[0];
        v0.y = (float)acc[i][1] * dq[1];
        v0.z = (float)acc[i][2] * dq[2];
        v0.w = (float)acc[i][3] * dq[3];
        v1.x = (float)acc[i][4] * dq[4];
        v1.y = (float)acc[i][5] * dq[5];
        v1.z = (float)acc[i][6] * dq[6];
        v1.w = (float)acc[i][7] * dq[7];
        *(float4*)Crow = v0;
        *(float4*)(Crow + 4) = v1;
    }
}

// ------------------------------------------------------------------
extern "C" void kernel_launch(void* const* d_in, const int* in_sizes, int n_in,
                              void* d_out, int out_size) {
    const float* act = (const float*)d_in[0];   // (8192, 4096)
    const float* w   = (const float*)d_in[1];   // (4096, 8192)
    float* out = (float*)d_out;                 // (8192, 8192)

    k_zero_bounds<<<(ND + 255) / 256, 256>>>();

    {
        dim3 g(KD / 256, MB / 512);
        k_act_absmax<<<g, 256>>>(act);
    }
    k_act_quant<<<4096, 256>>>(act);
    {
        dim3 g(ND / 256, KD / 256);
        k_w_absmax<<<g, 256>>>(w);
    }
    {
        dim3 g(ND / 32, KD / 32);
        dim3 b(32, 8);
        k_w_quant_T<<<g, b>>>(w);
    }
    {
        dim3 g(ND / 128, MB / 128);
        k_gemm_dp4a<<<g, 256>>>(out);
    }
}

// round 6
// speedup vs baseline: 2.9123x; 2.9123x over previous
#include <cuda_runtime.h>
#include <cuda_bf16.h>
#include <cstdint>

// act (8192 x 4096) f32, w (4096 x 8192) f32 -> out (8192 x 8192) f32
// int8-quantized GEMM reproducing the JAX reference.
// GEMM path: mma.sync m16n8k16 bf16 (fallback HMMA; tcgen05 is not available
// under this toolchain's compute_103 PTX target).

#define EPSQ 1e-6f
#define CLIPV 127.0f

#define MB 8192
#define KD 4096
#define ND 8192

#define BM 128
#define BN 128
#define BK 64                     // bf16 k-elements per tile (128 B rows)
#define STAGES 3
#define KTILES (KD / BK)          // 64
#define ASTAGE 16384              // 128 rows * 128 B
#define STAGE_BYTES 32768         // A + B
#define SMEM_GEMM (STAGES * STAGE_BYTES)

// ---------------- scratch ----------------
__device__ __align__(128) unsigned int g_amax[KD];
__device__ __align__(128) unsigned int g_wmax[ND];
__device__ __align__(128) __nv_bfloat16 g_actq[(size_t)MB * KD]; // [M][K]
__device__ __align__(128) __nv_bfloat16 g_wq[(size_t)ND * KD];   // [N][K]

// ---------------- helpers ----------------
__device__ __forceinline__ uint32_t smem_u32(const void* p) {
    uint32_t a;
    asm("{ .reg .u64 t; cvta.to.shared.u64 t, %1; cvt.u32.u64 %0, t; }" : "=r"(a) : "l"(p));
    return a;
}
#define SWZ128(o) ((o) ^ (((o) >> 3) & 0x70))
#define CP16(dst, src) \
    asm volatile("cp.async.cg.shared.global [%0], [%1], 16;" :: "r"(dst), "l"(src))
#define CP_COMMIT() asm volatile("cp.async.commit_group;" ::: "memory")
#define CP_WAIT1()  asm volatile("cp.async.wait_group 1;" ::: "memory")

#define LDSM_X4(r0, r1, r2, r3, a) \
    asm volatile("ldmatrix.sync.aligned.m8n8.x4.shared.b16 {%0,%1,%2,%3}, [%4];" \
        : "=r"(r0), "=r"(r1), "=r"(r2), "=r"(r3) : "r"(a))

#define MMA16816(c, a0, a1, a2, a3, b0, b1)                                      \
    asm volatile("mma.sync.aligned.m16n8k16.row.col.f32.bf16.bf16.f32 "          \
        "{%0,%1,%2,%3}, {%4,%5,%6,%7}, {%8,%9}, {%0,%1,%2,%3};"                  \
        : "+f"((c)[0]), "+f"((c)[1]), "+f"((c)[2]), "+f"((c)[3])                 \
        : "r"(a0), "r"(a1), "r"(a2), "r"(a3), "r"(b0), "r"(b1))

// ------------------------------------------------------------------
__global__ void k_zero_bounds() {
    int i = blockIdx.x * blockDim.x + threadIdx.x;
    if (i < KD) g_amax[i] = 0u;
    if (i < ND) g_wmax[i] = 0u;
}

__global__ void k_act_absmax(const float* __restrict__ act) {
    int c  = blockIdx.x * 256 + threadIdx.x;
    int r0 = blockIdx.y * 512;
    const float* p = act + (size_t)r0 * KD + c;
    float m = 0.f;
#pragma unroll 8
    for (int r = 0; r < 512; ++r)
        m = fmaxf(m, fabsf(p[(size_t)r * KD]));
    atomicMax(&g_amax[c], __float_as_uint(m));
}

__global__ void k_act_quant(const float* __restrict__ act) {
    const float4* a4 = (const float4*)act;
    __nv_bfloat162* q2 = (__nv_bfloat162*)g_actq;
    size_t n4 = (size_t)MB * KD / 4;
    size_t stride = (size_t)gridDim.x * blockDim.x;
    for (size_t idx = blockIdx.x * (size_t)blockDim.x + threadIdx.x; idx < n4; idx += stride) {
        float4 v = a4[idx];
        int c = (int)(idx & (KD / 4 - 1)) * 4;
        float s0 = CLIPV / (__uint_as_float(g_amax[c + 0]) + EPSQ);
        float s1 = CLIPV / (__uint_as_float(g_amax[c + 1]) + EPSQ);
        float s2 = CLIPV / (__uint_as_float(g_amax[c + 2]) + EPSQ);
        float s3 = CLIPV / (__uint_as_float(g_amax[c + 3]) + EPSQ);
        float q0 = fminf(fmaxf(rintf(v.x * s0), -CLIPV), CLIPV);
        float q1 = fminf(fmaxf(rintf(v.y * s1), -CLIPV), CLIPV);
        float q2f = fminf(fmaxf(rintf(v.z * s2), -CLIPV), CLIPV);
        float q3 = fminf(fmaxf(rintf(v.w * s3), -CLIPV), CLIPV);
        q2[idx * 2 + 0] = __floats2bfloat162_rn(q0, q1);
        q2[idx * 2 + 1] = __floats2bfloat162_rn(q2f, q3);
    }
}

__global__ void k_w_absmax(const float* __restrict__ w) {
    __shared__ float invs[256];
    int k0 = blockIdx.y * 256;
    {
        float am = __uint_as_float(g_amax[k0 + threadIdx.x]);
        float s  = CLIPV / (am + EPSQ);
        invs[threadIdx.x] = 1.0f / s;
    }
    __syncthreads();
    int n = blockIdx.x * 256 + threadIdx.x;
    const float* p = w + (size_t)k0 * ND + n;
    float m = 0.f;
#pragma unroll 8
    for (int k = 0; k < 256; ++k)
        m = fmaxf(m, fabsf(p[(size_t)k * ND] * invs[k]));
    atomicMax(&g_wmax[n], __float_as_uint(m));
}

__global__ void k_w_quant_T(const float* __restrict__ w) {
    __shared__ __nv_bfloat16 t[32][33];
    int n0 = blockIdx.x * 32, k0 = blockIdx.y * 32;
    int tx = threadIdx.x, ty = threadIdx.y;
    int n = n0 + tx;
    float ws = CLIPV / (__uint_as_float(g_wmax[n]) + EPSQ);
#pragma unroll
    for (int r = 0; r < 4; ++r) {
        int ki = ty * 4 + r;
        int k = k0 + ki;
        float am = __uint_as_float(g_amax[k]);
        float iv = 1.0f / (CLIPV / (am + EPSQ));
        float v = w[(size_t)k * ND + n] * iv;
        float q = fminf(fmaxf(rintf(v * ws), -CLIPV), CLIPV);
        t[ki][tx] = __float2bfloat16(q);
    }
    __syncthreads();
    int idx = ty * 32 + tx;
    int nl = idx >> 3;
    int wd = idx & 7;
    __nv_bfloat162 p0, p1;
    p0.x = t[wd * 4 + 0][nl]; p0.y = t[wd * 4 + 1][nl];
    p1.x = t[wd * 4 + 2][nl]; p1.y = t[wd * 4 + 3][nl];
    uint2 pk = make_uint2(*(uint32_t*)&p0, *(uint32_t*)&p1);
    *(uint2*)&g_wq[(size_t)(n0 + nl) * KD + k0 + wd * 4] = pk;
}

// ------------------------------------------------------------------
// GEMM: C[m][n] = dot(actq[m,:], wq[n,:]) * dequant(n)
// 128x128 block, 8 warps (2x4), warp tile 64x32, mma.sync m16n8k16 bf16.
// ------------------------------------------------------------------
__global__ void __launch_bounds__(256, 2) k_gemm_mma(float* __restrict__ C) {
    extern __shared__ char smem[];
    const uint32_t sbase = smem_u32(smem);
    const int tid = threadIdx.x;
    const int lane = tid & 31;
    const int w = tid >> 5;
    const int wm = w >> 2;          // 0..1
    const int wn = w & 3;           // 0..3

    // ---- block swizzle: supergroups of 8 m-tiles sweep all n ----
    const int NUM_N = ND / BN;      // 64
    const int GM = 8;
    int bid = blockIdx.x;
    int group = bid / (GM * NUM_N);
    int rem = bid % (GM * NUM_N);
    int m0 = (group * GM + (rem % GM)) * BM;
    int n0 = (rem / GM) * BN;

    // ---- cp.async source/dest precompute ----
    const int rowb = tid >> 3;      // 0..31
    const int ci = tid & 7;         // 16B chunk within 128B row
    const __nv_bfloat16* gA = g_actq + ((size_t)(m0 + rowb)) * KD + ci * 8;
    const __nv_bfloat16* gB = g_wq   + ((size_t)(n0 + rowb)) * KD + ci * 8;
    const uint32_t dA = SWZ128((uint32_t)(rowb * 128 + ci * 16));

#define LOAD_STAGE(s, t)                                                         \
    do {                                                                         \
        uint32_t _st = sbase + (s) * STAGE_BYTES;                                \
        const __nv_bfloat16* _ga = gA + (size_t)(t) * BK;                        \
        const __nv_bfloat16* _gb = gB + (size_t)(t) * BK;                        \
        _Pragma("unroll")                                                        \
        for (int i = 0; i < 4; ++i)                                              \
            CP16(_st + dA + i * 4096, _ga + (size_t)i * 32 * KD);                \
        _Pragma("unroll")                                                        \
        for (int i = 0; i < 4; ++i)                                              \
            CP16(_st + ASTAGE + dA + i * 4096, _gb + (size_t)i * 32 * KD);       \
    } while (0)

    float acc[4][4][4];
#pragma unroll
    for (int mi = 0; mi < 4; ++mi)
#pragma unroll
        for (int ni = 0; ni < 4; ++ni)
#pragma unroll
            for (int e = 0; e < 4; ++e) acc[mi][ni][e] = 0.f;

    LOAD_STAGE(0, 0);
    CP_COMMIT();
    LOAD_STAGE(1, 1);
    CP_COMMIT();

    // ldmatrix address components (constant across k-tiles except column)
    const int arow = wm * 64 + (lane & 15);
    const int acolsel = (lane >> 4) << 4;                       // 0 or 16 bytes
    const int brow = wn * 32 + (lane & 7) + ((lane >> 4) << 3);
    const int bcolsel = ((lane >> 3) & 1) << 4;

    for (int t = 0; t < KTILES; ++t) {
        CP_WAIT1();
        __syncthreads();
        if (t + 2 < KTILES) LOAD_STAGE((t + 2) % STAGES, t + 2);
        CP_COMMIT();

        uint32_t As = sbase + (t % STAGES) * STAGE_BYTES;
        uint32_t Bs = As + ASTAGE;
#pragma unroll
        for (int k16 = 0; k16 < 4; ++k16) {
            uint32_t a[4][4], b[2][4];
            int acol = k16 * 32 + acolsel;
            int bcol = k16 * 32 + bcolsel;
#pragma unroll
            for (int mi = 0; mi < 4; ++mi) {
                uint32_t ad = As + SWZ128((uint32_t)((arow + mi * 16) * 128 + acol));
                LDSM_X4(a[mi][0], a[mi][1], a[mi][2], a[mi][3], ad);
            }
#pragma unroll
            for (int nj = 0; nj < 2; ++nj) {
                uint32_t bd = Bs + SWZ128((uint32_t)((brow + nj * 16) * 128 + bcol));
                LDSM_X4(b[nj][0], b[nj][1], b[nj][2], b[nj][3], bd);
            }
#pragma unroll
            for (int mi = 0; mi < 4; ++mi)
#pragma unroll
                for (int ni = 0; ni < 4; ++ni)
                    MMA16816(acc[mi][ni], a[mi][0], a[mi][1], a[mi][2], a[mi][3],
                             b[ni >> 1][(ni & 1) * 2], b[ni >> 1][(ni & 1) * 2 + 1]);
        }
        __syncthreads();
    }

    // ---- epilogue: dequant by 1/w_scale[n], direct stores ----
    float dq0[4], dq1[4];
#pragma unroll
    for (int ni = 0; ni < 4; ++ni) {
        int n = n0 + wn * 32 + ni * 8 + (lane & 3) * 2;
        float b0 = __uint_as_float(g_wmax[n]);
        float b1 = __uint_as_float(g_wmax[n + 1]);
        dq0[ni] = 1.0f / (CLIPV / (b0 + EPSQ));
        dq1[ni] = 1.0f / (CLIPV / (b1 + EPSQ));
    }
#pragma unroll
    for (int mi = 0; mi < 4; ++mi) {
        int r0 = m0 + wm * 64 + mi * 16 + (lane >> 2);
#pragma unroll
        for (int ni = 0; ni < 4; ++ni) {
            int n = n0 + wn * 32 + ni * 8 + (lane & 3) * 2;
            float2 v0, v1;
            v0.x = acc[mi][ni][0] * dq0[ni];
            v0.y = acc[mi][ni][1] * dq1[ni];
            v1.x = acc[mi][ni][2] * dq0[ni];
            v1.y = acc[mi][ni][3] * dq1[ni];
            *(float2*)(C + (size_t)r0 * ND + n) = v0;
            *(float2*)(C + (size_t)(r0 + 8) * ND + n) = v1;
        }
    }
#undef LOAD_STAGE
}

// ------------------------------------------------------------------
extern "C" void kernel_launch(void* const* d_in, const int* in_sizes, int n_in,
                              void* d_out, int out_size) {
    const float* act = (const float*)d_in[0];
    const float* w   = (const float*)d_in[1];
    float* out = (float*)d_out;

    cudaFuncSetAttribute(k_gemm_mma, cudaFuncAttributeMaxDynamicSharedMemorySize,
                         SMEM_GEMM);

    k_zero_bounds<<<(ND + 255) / 256, 256>>>();
    {
        dim3 g(KD / 256, MB / 512);
        k_act_absmax<<<g, 256>>>(act);
    }
    k_act_quant<<<4096, 256>>>(act);
    {
        dim3 g(ND / 256, KD / 256);
        k_w_absmax<<<g, 256>>>(w);
    }
    {
        dim3 g(ND / 32, KD / 32);
        dim3 b(32, 8);
        k_w_quant_T<<<g, b>>>(w);
    }
    {
        int nblocks = (MB / BM) * (ND / BN);
        k_gemm_mma<<<nblocks, 256, SMEM_GEMM>>>(out);
    }
}